// round 3
// baseline (speedup 1.0000x reference)
#include <cuda_runtime.h>
#include <math_constants.h>

#define B 8
#define T 200
#define U 50
#define V 1024

// Per-batch negative final log-prob
__device__ float g_partial[B];

__device__ __forceinline__ float logaddexpf_(float a, float b) {
    float m = fmaxf(a, b);
    float n = fminf(a, b);
    return m + __logf(1.0f + __expf(n - m));
}

// One block per batch element.
// Phase 1 (all 16 warps): gather blank/emit columns of h, compute logsumexp over T
//                         (softmax axis is T in the reference!), stage normalized
//                         log-probs into shared memory.
// Phase 2 (warp 0 only):  warp-synchronous anti-diagonal wavefront DP, 2 u-columns
//                         per lane, neighbor comm via shfl_up. No barriers in loop.
__global__ __launch_bounds__(512, 1) void rnnt_fused_kernel(
    const float* __restrict__ h,
    const int*   __restrict__ targets,      // (B, U-1)
    const int*   __restrict__ input_lens,   // (B,)
    const int*   __restrict__ target_lens)  // (B,)
{
    extern __shared__ float smem[];
    float* sblank = smem;            // [U][T]   blank[t][u] at sblank[u*T + t]
    float* semit  = smem + U * T;    // [U-1][T] emit[t][u]  at semit[u*T + t]

    const int b    = blockIdx.x;
    const int tid  = threadIdx.x;
    const int wid  = tid >> 5;
    const int lane = tid & 31;
    const int nwarps = blockDim.x >> 5;

    // ---------------- Phase 1: gather + logsumexp over T ----------------
    // Columns: c in [0, U)       -> blank column (u=c, v=0)
    //          c in [U, 2U-1)    -> emit column  (u=c-U, v=targets[b][u])
    for (int c = wid; c < U + (U - 1); c += nwarps) {
        int u;
        int v;
        float* dst;
        if (c < U) { u = c;     v = 0;                          dst = sblank + u * T; }
        else       { u = c - U; v = targets[b * (U - 1) + u];   dst = semit  + u * T; }

        const float* col = h + (size_t)b * T * U * V + (size_t)u * V + v;
        // t-stride in elements:
        const size_t tstride = (size_t)U * V;

        float x[7];
        #pragma unroll
        for (int k = 0; k < 7; k++) {
            int t = lane + 32 * k;
            x[k] = (t < T) ? col[(size_t)t * tstride] : -CUDART_INF_F;
        }
        // warp logsumexp
        float m = x[0];
        #pragma unroll
        for (int k = 1; k < 7; k++) m = fmaxf(m, x[k]);
        #pragma unroll
        for (int o = 16; o > 0; o >>= 1) m = fmaxf(m, __shfl_xor_sync(0xffffffff, m, o));
        float s = 0.0f;
        #pragma unroll
        for (int k = 0; k < 7; k++) s += __expf(x[k] - m);   // exp(-inf - m) -> 0
        #pragma unroll
        for (int o = 16; o > 0; o >>= 1) s += __shfl_xor_sync(0xffffffff, s, o);
        float lse = m + __logf(s);

        #pragma unroll
        for (int k = 0; k < 7; k++) {
            int t = lane + 32 * k;
            if (t < T) dst[t] = x[k] - lse;
        }
    }
    __syncthreads();
    if (wid != 0) return;

    // ---------------- Phase 2: wavefront DP (warp 0) ----------------
    // alpha[0][0] = 0
    // alpha[0][u] = alpha[0][u-1] + emit[0][u-1]
    // alpha[t][0] = alpha[t-1][0] + blank[t-1][0]
    // alpha[t][u] = logaddexp(alpha[t-1][u] + blank[t-1][u],
    //                         alpha[t][u-1] + emit[t][u-1])
    // Lane l owns u0=2l, u1=2l+1. On diagonal d: t0=d-u0, t1=d-u1=t0-1.
    //   new0 nbr term:  alpha[t0][u0-1] = lane(l-1)'s prev1   (shfl_up)
    //   new1 nbr term:  alpha[t1][u1-1] = own prev0
    const int ti = input_lens[b]  - 1;
    const int ui = target_lens[b] - 1;
    const int u0 = 2 * lane;
    const int u1 = u0 + 1;

    float prev0 = 0.0f, prev1 = 0.0f;
    float fin = 0.0f;
    const int dmax = ti + ui;

    for (int d = 0; d <= dmax; d++) {
        float nbr0 = __shfl_up_sync(0xffffffff, prev1, 1);
        int t0 = d - u0;
        int t1 = t0 - 1;
        float new0 = prev0, new1 = prev1;

        if (u0 < U && t0 >= 0 && t0 < T) {
            if (t0 == 0)       new0 = (u0 == 0) ? 0.0f : nbr0 + semit[(u0 - 1) * T];
            else if (u0 == 0)  new0 = prev0 + sblank[t0 - 1];
            else               new0 = logaddexpf_(prev0 + sblank[u0 * T + t0 - 1],
                                                  nbr0  + semit[(u0 - 1) * T + t0]);
            if (t0 == ti && u0 == ui) fin = new0 + sblank[ui * T + ti];
        }
        if (u1 < U && t1 >= 0 && t1 < T) {
            if (t1 == 0)       new1 = prev0 + semit[u0 * T];
            else               new1 = logaddexpf_(prev1 + sblank[u1 * T + t1 - 1],
                                                  prev0 + semit[u0 * T + t1]);
            if (t1 == ti && u1 == ui) fin = new1 + sblank[ui * T + ti];
        }
        prev0 = new0;
        prev1 = new1;
    }

    if (lane == (ui >> 1)) g_partial[b] = -fin;
}

__global__ void rnnt_mean_kernel(float* __restrict__ out) {
    float s = 0.0f;
    #pragma unroll
    for (int i = 0; i < B; i++) s += g_partial[i];
    out[0] = s * (1.0f / B);
}

extern "C" void kernel_launch(void* const* d_in, const int* in_sizes, int n_in,
                              void* d_out, int out_size) {
    const float* h           = (const float*)d_in[0];
    const int*   targets     = (const int*)d_in[1];
    const int*   input_lens  = (const int*)d_in[2];
    const int*   target_lens = (const int*)d_in[3];
    float*       out         = (float*)d_out;

    const size_t smem_bytes = (size_t)(U * T + (U - 1) * T) * sizeof(float); // 79200 B
    cudaFuncSetAttribute(rnnt_fused_kernel,
                         cudaFuncAttributeMaxDynamicSharedMemorySize,
                         (int)smem_bytes);

    rnnt_fused_kernel<<<B, 512, smem_bytes>>>(h, targets, input_lens, target_lens);
    rnnt_mean_kernel<<<1, 1>>>(out);
}

// round 4
// speedup vs baseline: 3.6923x; 3.6923x over previous
#include <cuda_runtime.h>
#include <math_constants.h>

#define B 8
#define T 200
#define U 50
#define V 1024

#define NCOL   99          // 50 blank cols + 49 emit cols
#define TP     320         // padded column length
#define FRONT  52          // front padding (-inf), covers t as low as -50
#define DUMMY  99          // all -inf column
#define NCOLS  100         // NCOL + dummy

#define LOG2E 1.4426950408889634f
#define LN2   0.6931471805599453f
#define NEGINF (-CUDART_INF_F)

// (x - lse) * log2e, compact layout [b][col][t], col<50 = blank(u=col), col>=50 = emit(u=col-50)
__device__ float g_scratch[B * NCOL * T];
__device__ float g_partial[B];

// base-2 logaddexp: m + log2(1 + 2^(min-m))
__device__ __forceinline__ float la2(float a, float b) {
    float m = fmaxf(a, b);
    float d = fminf(a, b) - m;          // <= 0  (or -inf / NaN on dead cells)
    float e;
    asm("ex2.approx.ftz.f32 %0, %1;" : "=f"(e) : "f"(d));
    float l;
    asm("lg2.approx.ftz.f32 %0, %1;" : "=f"(l) : "f"(1.0f + e));
    return m + l;
}

// ---------------------------------------------------------------------------
// Kernel A: one warp per (batch, column). Gather the strided h column,
// logsumexp over T (softmax axis is T!), write normalized log2-scaled values.
// grid = B*NCOL blocks x 32 threads -> spreads DRAM traffic over the chip.
// ---------------------------------------------------------------------------
__global__ __launch_bounds__(32) void rnnt_gather_kernel(
    const float* __restrict__ h,
    const int*   __restrict__ targets)   // (B, U-1)
{
    const int blk  = blockIdx.x;
    const int b    = blk / NCOL;
    const int c    = blk - b * NCOL;
    const int lane = threadIdx.x;

    int u, v;
    if (c < U) { u = c;     v = 0; }
    else       { u = c - U; v = targets[b * (U - 1) + u]; }

    const float* col = h + (size_t)b * T * U * V + (size_t)u * V + v;
    const size_t tstride = (size_t)U * V;

    float x[7];
    #pragma unroll
    for (int k = 0; k < 7; k++) {
        int t = lane + 32 * k;
        x[k] = (t < T) ? col[(size_t)t * tstride] : NEGINF;
    }
    float m = x[0];
    #pragma unroll
    for (int k = 1; k < 7; k++) m = fmaxf(m, x[k]);
    #pragma unroll
    for (int o = 16; o > 0; o >>= 1) m = fmaxf(m, __shfl_xor_sync(0xffffffff, m, o));
    float s = 0.0f;
    #pragma unroll
    for (int k = 0; k < 7; k++) s += __expf(x[k] - m);
    #pragma unroll
    for (int o = 16; o > 0; o >>= 1) s += __shfl_xor_sync(0xffffffff, s, o);
    const float lse = m + __logf(s);

    float* dst = g_scratch + (size_t)(b * NCOL + c) * T;
    #pragma unroll
    for (int k = 0; k < 7; k++) {
        int t = lane + 32 * k;
        if (t < T) dst[t] = (x[k] - lse) * LOG2E;
    }
}

// ---------------------------------------------------------------------------
// Kernel B: one block per batch. Stage padded -inf-bordered columns in smem,
// then warp 0 runs a branch-free anti-diagonal wavefront DP (2 u per lane).
//
// Padded layout, column stride TP:
//   col u      (u<50):  blank[t][u] at  u*TP      + FRONT + t + 1
//   col 50+u   (u<49):  emit[t][u]  at (50+u)*TP  + FRONT + t
//   col DUMMY:          all -inf
// Cell (t0,u0) on diagonal d (t0 = d-u0) reads BOTH its blank[t0-1] term and
// its emit[t0] term at flat offset  col_base + FRONT + (d - u).
// ---------------------------------------------------------------------------
__global__ __launch_bounds__(512, 1) void rnnt_dp_kernel(
    const int* __restrict__ input_lens,
    const int* __restrict__ target_lens)
{
    extern __shared__ float smem[];
    const int b   = blockIdx.x;
    const int tid = threadIdx.x;

    // 1) flood with -inf (covers all padding + dummy column)
    for (int i = tid; i < NCOLS * TP; i += 512) smem[i] = NEGINF;
    __syncthreads();

    // 2) coalesced fill of valid region from scratch (L2-resident)
    const float* src = g_scratch + (size_t)b * NCOL * T;
    for (int i = tid; i < NCOL * T; i += 512) {
        int col = i / T;
        int t   = i - col * T;
        smem[col * TP + FRONT + t + (col < U ? 1 : 0)] = src[i];
    }
    __syncthreads();
    if (tid >= 32) return;

    // ---- wavefront DP, warp-synchronous, branch-free ----
    const int lane = tid;
    const int ti = input_lens[b]  - 1;
    const int ui = target_lens[b] - 1;
    const int u0 = 2 * lane;
    const int u1 = u0 + 1;

    const bool v0 = (u0 < U);
    const bool v1 = (u1 < U);

    const float* B0 = smem + (v0            ? u0 * TP       - u0 : DUMMY * TP) + FRONT;
    const float* E0 = smem + ((v0 && u0 > 0) ? (U + u0 - 1) * TP - u0 : DUMMY * TP) + FRONT;
    const float* B1 = smem + (v1            ? u1 * TP       - u1 : DUMMY * TP) + FRONT;
    const float* E1 = smem + (v1            ? (U + u0) * TP - u1 : DUMMY * TP) + FRONT;

    float prev0 = (lane == 0) ? 0.0f : NEGINF;   // alpha[0][0] = 0
    float prev1 = NEGINF;
    const int dmax = ti + ui;

    float b0 = B0[1], e0 = E0[1], b1 = B1[1], e1 = E1[1];
    for (int d = 1; d <= dmax; d++) {
        // prefetch next diagonal's smem values under the la2 chain
        float nb0 = B0[d + 1], ne0 = E0[d + 1], nb1 = B1[d + 1], ne1 = E1[d + 1];

        float nbr = __shfl_up_sync(0xffffffff, prev1, 1);
        nbr = (lane == 0) ? NEGINF : nbr;

        float new0 = la2(prev0 + b0, nbr   + e0);
        float new1 = la2(prev1 + b1, prev0 + e1);

        prev0 = new0; prev1 = new1;
        b0 = nb0; e0 = ne0; b1 = nb1; e1 = ne1;
    }

    // cell (ti,ui) is computed exactly on diagonal dmax by lane ui>>1
    if (lane == (ui >> 1)) {
        float res  = (ui & 1) ? prev1 : prev0;
        float bfin = smem[ui * TP + FRONT + ti + 1];   // blank[ti][ui] (log2-scaled)
        g_partial[b] = -(res + bfin) * LN2;
    }
}

__global__ void rnnt_mean_kernel(float* __restrict__ out) {
    float s = 0.0f;
    #pragma unroll
    for (int i = 0; i < B; i++) s += g_partial[i];
    out[0] = s * (1.0f / B);
}

extern "C" void kernel_launch(void* const* d_in, const int* in_sizes, int n_in,
                              void* d_out, int out_size) {
    const float* h           = (const float*)d_in[0];
    const int*   targets     = (const int*)d_in[1];
    const int*   input_lens  = (const int*)d_in[2];
    const int*   target_lens = (const int*)d_in[3];
    float*       out         = (float*)d_out;

    const size_t smem_bytes = (size_t)NCOLS * TP * sizeof(float);   // 128000 B
    static int smem_set = 0;
    if (!smem_set) {
        cudaFuncSetAttribute(rnnt_dp_kernel,
                             cudaFuncAttributeMaxDynamicSharedMemorySize,
                             (int)smem_bytes);
        smem_set = 1;
    }

    rnnt_gather_kernel<<<B * NCOL, 32>>>(h, targets);
    rnnt_dp_kernel<<<B, 512, smem_bytes>>>(input_lens, target_lens);
    rnnt_mean_kernel<<<1, 1>>>(out);
}